// round 3
// baseline (speedup 1.0000x reference)
#include <cuda_runtime.h>
#include <math.h>

#define BATCH 4096
#define TSTEPS 60
#define FDIM 128
#define HDIM 256
#define FH 384

#define BM 64
#define BN 64
#define BK 32

// Scratch (allocation-free rule: __device__ globals)
__device__ float g_h[2][(size_t)BATCH * HDIM];  // ping-pong hidden state
__device__ float g_c[(size_t)BATCH * HDIM];     // cell state (in-place)
__device__ float g_weff[HDIM];
__device__ float g_beff;

__device__ __forceinline__ float sigmoidf_(float x) {
    return 1.0f / (1.0f + __expf(-x));
}

__global__ void init_state_kernel() {
    size_t i = (size_t)blockIdx.x * blockDim.x + threadIdx.x;
    size_t n = (size_t)BATCH * HDIM;
    if (i < n) {
        g_h[0][i] = 0.0f;
        g_c[i] = 0.0f;
    }
}

// Collapse the activation-free dense head: w_eff = Wd1 @ Wd2, b_eff = bd1 . Wd2 + bd2
__global__ void weff_kernel(const float* __restrict__ Wd1, const float* __restrict__ bd1,
                            const float* __restrict__ Wd2, const float* __restrict__ bd2) {
    int i = threadIdx.x;  // 0..255
    float s = 0.0f;
    #pragma unroll 8
    for (int j = 0; j < HDIM; ++j) s += Wd1[(size_t)i * HDIM + j] * Wd2[j];
    g_weff[i] = s;
    if (i == 0) {
        float b = 0.0f;
        for (int j = 0; j < HDIM; ++j) b += bd1[j] * Wd2[j];
        g_beff = b + bd2[0];
    }
}

// One LSTM step: gates = [x_t, h_prev] @ W* + b*, fused elementwise update.
// Block: BM=64 batch rows x BN=64 hidden cols, all 4 gates.
__global__ __launch_bounds__(256, 2)
void lstm_step_kernel(const float* __restrict__ x,
                      const float* __restrict__ Wf, const float* __restrict__ bf,
                      const float* __restrict__ Wu, const float* __restrict__ bu,
                      const float* __restrict__ Wc, const float* __restrict__ bc,
                      const float* __restrict__ Wo, const float* __restrict__ bo,
                      int t) {
    __shared__ float zT[BK][BM + 1];    // [32][65] K-major z tile (pad -> conflict-free)
    __shared__ float Ws[4][BK][BN];     // [4][32][64] weight tiles (f,u,c,o)

    const int tid = threadIdx.x;
    const int ty = tid >> 4;    // 0..15 -> 4 batch rows each
    const int tx = tid & 15;    // 0..15 -> 4 hidden cols each
    const int b0 = blockIdx.x * BM;
    const int n0 = blockIdx.y * BN;

    const float* __restrict__ hr = g_h[t & 1];
    float* __restrict__ hw = g_h[(t + 1) & 1];

    float acc[4][4][4];
    #pragma unroll
    for (int g = 0; g < 4; ++g)
        #pragma unroll
        for (int i = 0; i < 4; ++i)
            #pragma unroll
            for (int j = 0; j < 4; ++j) acc[g][i][j] = 0.0f;

    for (int koff = 0; koff < FH; koff += BK) {
        // ---- load z tile (transposed): rows from x_t (k<128) or h_prev (k>=128)
        #pragma unroll
        for (int it = 0; it < 2; ++it) {
            int idx = it * 256 + tid;      // 0..511
            int row = idx >> 3;            // 0..63
            int kq  = idx & 7;             // float4 index in the 32-wide K chunk
            int k   = koff + kq * 4;
            float4 v;
            if (koff < FDIM) {
                v = *(const float4*)&x[((size_t)(b0 + row) * TSTEPS + t) * FDIM + k];
            } else {
                v = *(const float4*)&hr[(size_t)(b0 + row) * HDIM + (k - FDIM)];
            }
            zT[kq * 4 + 0][row] = v.x;
            zT[kq * 4 + 1][row] = v.y;
            zT[kq * 4 + 2][row] = v.z;
            zT[kq * 4 + 3][row] = v.w;
        }
        // ---- load 4 weight tiles [32][64] each
        #pragma unroll
        for (int it = 0; it < 8; ++it) {
            const float* __restrict__ Wp = (it < 2) ? Wf : (it < 4) ? Wu : (it < 6) ? Wc : Wo;
            const int g = it >> 1;
            int rem = (it & 1) * 256 + tid;   // 0..511 float4s within this gate's tile
            int kk = rem >> 4;                // 0..31
            int cq = rem & 15;                // 0..15
            float4 v = *(const float4*)&Wp[(size_t)(koff + kk) * HDIM + n0 + cq * 4];
            *(float4*)&Ws[g][kk][cq * 4] = v;
        }
        __syncthreads();

        // ---- 64 FMA per kk per thread
        #pragma unroll 8
        for (int kk = 0; kk < BK; ++kk) {
            float a[4];
            #pragma unroll
            for (int i = 0; i < 4; ++i) a[i] = zT[kk][ty * 4 + i];
            #pragma unroll
            for (int g = 0; g < 4; ++g) {
                float4 bv = *(const float4*)&Ws[g][kk][tx * 4];
                #pragma unroll
                for (int i = 0; i < 4; ++i) {
                    acc[g][i][0] = fmaf(a[i], bv.x, acc[g][i][0]);
                    acc[g][i][1] = fmaf(a[i], bv.y, acc[g][i][1]);
                    acc[g][i][2] = fmaf(a[i], bv.z, acc[g][i][2]);
                    acc[g][i][3] = fmaf(a[i], bv.w, acc[g][i][3]);
                }
            }
        }
        __syncthreads();
    }

    // ---- epilogue: biases + gates + state update
    const int nb = n0 + tx * 4;
    float4 bf4 = *(const float4*)&bf[nb];
    float4 bu4 = *(const float4*)&bu[nb];
    float4 bc4 = *(const float4*)&bc[nb];
    float4 bo4 = *(const float4*)&bo[nb];
    float bfA[4] = {bf4.x, bf4.y, bf4.z, bf4.w};
    float buA[4] = {bu4.x, bu4.y, bu4.z, bu4.w};
    float bcA[4] = {bc4.x, bc4.y, bc4.z, bc4.w};
    float boA[4] = {bo4.x, bo4.y, bo4.z, bo4.w};

    #pragma unroll
    for (int i = 0; i < 4; ++i) {
        int r = b0 + ty * 4 + i;
        size_t base = (size_t)r * HDIM + nb;
        float4 c4 = *(float4*)&g_c[base];
        float cv[4] = {c4.x, c4.y, c4.z, c4.w};
        float hn[4];
        #pragma unroll
        for (int j = 0; j < 4; ++j) {
            float fv = sigmoidf_(acc[0][i][j] + bfA[j]);
            float uv = sigmoidf_(acc[1][i][j] + buA[j]);
            float gv = tanhf(acc[2][i][j] + bcA[j]);
            float ov = sigmoidf_(acc[3][i][j] + boA[j]);
            float cn = fv * cv[j] + uv * gv;
            cv[j] = cn;
            hn[j] = ov * tanhf(cn);
        }
        *(float4*)&g_c[base] = make_float4(cv[0], cv[1], cv[2], cv[3]);
        *(float4*)&hw[base]  = make_float4(hn[0], hn[1], hn[2], hn[3]);
    }
}

// out[b] = h_final[b] . w_eff + b_eff. One warp per batch row.
__global__ void head_kernel(float* __restrict__ out) {
    int w = threadIdx.x >> 5;
    int lane = threadIdx.x & 31;
    int r = blockIdx.x * 8 + w;
    if (r >= BATCH) return;
    const float* __restrict__ hrow = g_h[TSTEPS & 1] + (size_t)r * HDIM;
    float s = 0.0f;
    #pragma unroll
    for (int k = lane; k < HDIM; k += 32) s += hrow[k] * g_weff[k];
    #pragma unroll
    for (int off = 16; off > 0; off >>= 1) s += __shfl_down_sync(0xffffffffu, s, off);
    if (lane == 0) out[r] = s + g_beff;
}

extern "C" void kernel_launch(void* const* d_in, const int* in_sizes, int n_in,
                              void* d_out, int out_size) {
    const float* x   = (const float*)d_in[0];
    const float* Wf  = (const float*)d_in[1];
    const float* bf  = (const float*)d_in[2];
    const float* Wu  = (const float*)d_in[3];
    const float* bu  = (const float*)d_in[4];
    const float* Wc  = (const float*)d_in[5];
    const float* bc  = (const float*)d_in[6];
    const float* Wo  = (const float*)d_in[7];
    const float* bo  = (const float*)d_in[8];
    const float* Wd1 = (const float*)d_in[9];
    const float* bd1 = (const float*)d_in[10];
    const float* Wd2 = (const float*)d_in[11];
    const float* bd2 = (const float*)d_in[12];
    float* out = (float*)d_out;

    init_state_kernel<<<(BATCH * HDIM + 255) / 256, 256>>>();
    weff_kernel<<<1, HDIM>>>(Wd1, bd1, Wd2, bd2);

    dim3 grid(BATCH / BM, HDIM / BN);
    for (int t = 0; t < TSTEPS; ++t) {
        lstm_step_kernel<<<grid, 256>>>(x, Wf, bf, Wu, bu, Wc, bc, Wo, bo, t);
    }

    head_kernel<<<BATCH / 8, 256>>>(out);
}

// round 5
// speedup vs baseline: 1.6947x; 1.6947x over previous
#include <cuda_runtime.h>
#include <cuda_fp16.h>
#include <math.h>
#include <cstdint>

#define BATCH 4096
#define TSTEPS 60
#define FDIM 128
#define HDIM 256
#define FH 384

// ---------------- device scratch (allocation-free rule) ----------------
__device__ __half g_xh[(size_t)BATCH * TSTEPS * FDIM];
__device__ __half g_xl[(size_t)BATCH * TSTEPS * FDIM];
__device__ __half g_hh[2][(size_t)BATCH * HDIM];
__device__ __half g_hl[2][(size_t)BATCH * HDIM];
__device__ float  g_c[(size_t)BATCH * HDIM];
__device__ __half g_Wh[(size_t)1024 * FH];   // [gate*256+col][k]
__device__ __half g_Wl[(size_t)1024 * FH];
__device__ float  g_weff[HDIM];
__device__ float  g_beff;

__device__ __forceinline__ float sigmoidf_(float x) { return 1.0f / (1.0f + __expf(-x)); }

__device__ __forceinline__ uint32_t smem_u32(const void* p) {
    uint32_t a;
    asm("{ .reg .u64 t; cvta.to.shared.u64 t, %1; cvt.u32.u64 %0, t; }" : "=r"(a) : "l"(p));
    return a;
}

#define LD4(R, ADDR) \
    asm volatile("ldmatrix.sync.aligned.m8n8.x4.shared.b16 {%0,%1,%2,%3}, [%4];" \
        : "=r"((R)[0]), "=r"((R)[1]), "=r"((R)[2]), "=r"((R)[3]) : "r"(ADDR))

#define MMA16816(C, A, B0, B1) \
    asm volatile("mma.sync.aligned.m16n8k16.row.col.f32.f16.f16.f32 " \
        "{%0,%1,%2,%3}, {%4,%5,%6,%7}, {%8,%9}, {%0,%1,%2,%3};" \
        : "+f"((C)[0]), "+f"((C)[1]), "+f"((C)[2]), "+f"((C)[3]) \
        : "r"((A)[0]), "r"((A)[1]), "r"((A)[2]), "r"((A)[3]), "r"(B0), "r"(B1))

// ---------------- prep kernels ----------------
__global__ void init_state_kernel() {
    size_t i = (size_t)blockIdx.x * blockDim.x + threadIdx.x;
    if (i < (size_t)BATCH * HDIM) {
        g_hh[0][i] = __float2half(0.0f);
        g_hl[0][i] = __float2half(0.0f);
        g_c[i] = 0.0f;
    }
}

__global__ void split_x_kernel(const float* __restrict__ x) {
    size_t i = (size_t)blockIdx.x * blockDim.x + threadIdx.x;
    if (i < (size_t)BATCH * TSTEPS * FDIM) {
        float v = x[i];
        __half hi = __float2half(v);
        g_xh[i] = hi;
        g_xl[i] = __float2half(v - __half2float(hi));
    }
}

__global__ void build_WT_kernel(const float* __restrict__ Wf, const float* __restrict__ Wu,
                                const float* __restrict__ Wc, const float* __restrict__ Wo) {
    int gr = blockIdx.x;                 // 0..1023
    int g = gr >> 8, col = gr & 255;
    const float* W = (g == 0) ? Wf : (g == 1) ? Wu : (g == 2) ? Wc : Wo;
    for (int k = threadIdx.x; k < FH; k += blockDim.x) {
        float w = W[(size_t)k * HDIM + col];
        __half hi = __float2half(w);
        g_Wh[(size_t)gr * FH + k] = hi;
        g_Wl[(size_t)gr * FH + k] = __float2half(w - __half2float(hi));
    }
}

__global__ void weff_kernel(const float* __restrict__ Wd1, const float* __restrict__ bd1,
                            const float* __restrict__ Wd2, const float* __restrict__ bd2) {
    int i = threadIdx.x;
    float s = 0.0f;
    #pragma unroll 8
    for (int j = 0; j < HDIM; ++j) s += Wd1[(size_t)i * HDIM + j] * Wd2[j];
    g_weff[i] = s;
    if (i == 0) {
        float b = 0.0f;
        for (int j = 0; j < HDIM; ++j) b += bd1[j] * Wd2[j];
        g_beff = b + bd2[0];
    }
}

// ---------------- step kernel (mma.sync fp16x3) ----------------
// smem buffer layout (stride 80B rows for conflict-free ldmatrix):
#define A_HI 0
#define A_LO 10240
#define B_HI 20480
#define B_LO 40960
#define BUF_SZ 61440
#define SMEM_TOTAL (2 * BUF_SZ)   // 120 KB; epilogue S (64KB) reuses front

__global__ __launch_bounds__(256, 1)
void lstm_step_mma(const float* __restrict__ bfv, const float* __restrict__ buv,
                   const float* __restrict__ bcv, const float* __restrict__ bov, int t) {
    extern __shared__ __align__(128) char smem[];
    const uint32_t sbase = smem_u32(smem);
    const int tid = threadIdx.x;
    const int warp = tid >> 5;
    const int lane = tid & 31;
    const int wm = warp >> 2;      // 0..1 : m-half
    const int wg = warp & 3;       // gate
    const int m0 = blockIdx.x * 128;
    const int ny = blockIdx.y;     // hidden slice (64 cols)

    const __half* __restrict__ hhr = g_hh[t & 1];
    const __half* __restrict__ hlr = g_hl[t & 1];
    __half* __restrict__ hhw = g_hh[(t + 1) & 1];
    __half* __restrict__ hlw = g_hl[(t + 1) & 1];

    float acc[4][8][4];
    #pragma unroll
    for (int i = 0; i < 4; ++i)
        #pragma unroll
        for (int j = 0; j < 8; ++j)
            #pragma unroll
            for (int q = 0; q < 4; ++q) acc[i][j][q] = 0.0f;

    // -------- chunk loader (c in 0..11, K chunk = 32) --------
    auto load_chunk = [&](int c) {
        char* bb = smem + (c & 1) * BUF_SZ;
        // A: 128 rows x 32 k (fp16 hi/lo). thread: row tid>>1, 16-halves half tid&1
        int r = tid >> 1, hs = tid & 1;
        size_t s;
        const __half *ph, *pl;
        if (c < 4) {
            s = ((size_t)(m0 + r) * TSTEPS + t) * FDIM + c * 32 + hs * 16;
            ph = g_xh; pl = g_xl;
        } else {
            s = (size_t)(m0 + r) * HDIM + (c - 4) * 32 + hs * 16;
            ph = hhr; pl = hlr;
        }
        uint4 v0 = *(const uint4*)&ph[s];
        uint4 v1 = *(const uint4*)&ph[s + 8];
        uint4 w0 = *(const uint4*)&pl[s];
        uint4 w1 = *(const uint4*)&pl[s + 8];
        char* da = bb + A_HI + r * 80 + hs * 32;
        *(uint4*)(da) = v0; *(uint4*)(da + 16) = v1;
        char* dl = bb + A_LO + r * 80 + hs * 32;
        *(uint4*)(dl) = w0; *(uint4*)(dl + 16) = w1;
        // B: 256 rows (4 gates x 64 cols) x 32 k. thread: row tid, 32 halves
        int n = tid;
        int gr = ((n >> 6) << 8) + ny * 64 + (n & 63);
        size_t sb2 = (size_t)gr * FH + c * 32;
        char* db  = bb + B_HI + n * 80;
        char* dbl = bb + B_LO + n * 80;
        #pragma unroll
        for (int q = 0; q < 4; ++q) {
            *(uint4*)(db + q * 16)  = *(const uint4*)&g_Wh[sb2 + q * 8];
            *(uint4*)(dbl + q * 16) = *(const uint4*)&g_Wl[sb2 + q * 8];
        }
    };

    const int grp = lane >> 3, lr = lane & 7;

    load_chunk(0);
    __syncthreads();

    for (int c = 0; c < 12; ++c) {
        if (c + 1 < 12) load_chunk(c + 1);

        const uint32_t bufb = sbase + (uint32_t)((c & 1) * BUF_SZ);
        #pragma unroll
        for (int kh = 0; kh < 2; ++kh) {
            uint32_t ah[4][4], al[4][4], bh[4][4], bl[4][4];
            const int acol = kh * 32 + (grp >> 1) * 16;
            #pragma unroll
            for (int i = 0; i < 4; ++i) {
                int arow = wm * 64 + i * 16 + (grp & 1) * 8 + lr;
                uint32_t ad = bufb + A_HI + (uint32_t)(arow * 80 + acol);
                LD4(ah[i], ad);
                LD4(al[i], ad + (A_LO - A_HI));
            }
            const int bcol = kh * 32 + (grp & 1) * 16;
            #pragma unroll
            for (int j = 0; j < 4; ++j) {
                int brow = wg * 64 + j * 16 + ((grp >> 1) << 3) + lr;
                uint32_t bd = bufb + B_HI + (uint32_t)(brow * 80 + bcol);
                LD4(bh[j], bd);
                LD4(bl[j], bd + (B_LO - B_HI));
            }
            #pragma unroll
            for (int i = 0; i < 4; ++i)
                #pragma unroll
                for (int j = 0; j < 4; ++j)
                    #pragma unroll
                    for (int s2 = 0; s2 < 2; ++s2) {
                        const int nb = j * 2 + s2;
                        MMA16816(acc[i][nb], ah[i], bh[j][s2 * 2], bh[j][s2 * 2 + 1]);
                        MMA16816(acc[i][nb], ah[i], bl[j][s2 * 2], bl[j][s2 * 2 + 1]);
                        MMA16816(acc[i][nb], al[i], bh[j][s2 * 2], bh[j][s2 * 2 + 1]);
                    }
        }
        __syncthreads();
    }

    // -------- epilogue: exchange gate slabs via smem, fused LSTM update --------
    float* S = (float*)smem;   // S[gate][64][64] fp32 = 64 KB
    for (int ph2 = 0; ph2 < 2; ++ph2) {
        if (wm == ph2) {
            #pragma unroll
            for (int i = 0; i < 4; ++i)
                #pragma unroll
                for (int nb = 0; nb < 8; ++nb) {
                    int rr = i * 16 + (lane >> 2);
                    int cc = nb * 8 + (lane & 3) * 2;
                    float* p0 = &S[((wg * 64 + rr) * 64) + cc];
                    p0[0] = acc[i][nb][0];
                    p0[1] = acc[i][nb][1];
                    float* p1 = &S[((wg * 64 + rr + 8) * 64) + cc];
                    p1[0] = acc[i][nb][2];
                    p1[1] = acc[i][nb][3];
                }
        }
        __syncthreads();

        const int r = tid >> 2;
        const int cg = (tid & 3) * 16;
        const int m = m0 + ph2 * 64 + r;
        #pragma unroll
        for (int q = 0; q < 4; ++q) {
            const int cc = cg + q * 4;
            const int col = ny * 64 + cc;
            const size_t gidx = (size_t)m * HDIM + col;
            float4 fx = *(float4*)&S[(0 * 64 + r) * 64 + cc];
            float4 ux = *(float4*)&S[(1 * 64 + r) * 64 + cc];
            float4 gx = *(float4*)&S[(2 * 64 + r) * 64 + cc];
            float4 ox = *(float4*)&S[(3 * 64 + r) * 64 + cc];
            float4 bF = *(const float4*)&bfv[col];
            float4 bU = *(const float4*)&buv[col];
            float4 bC = *(const float4*)&bcv[col];
            float4 bO = *(const float4*)&bov[col];
            float4 c4 = *(float4*)&g_c[gidx];
            float fa[4] = {fx.x + bF.x, fx.y + bF.y, fx.z + bF.z, fx.w + bF.w};
            float ua[4] = {ux.x + bU.x, ux.y + bU.y, ux.z + bU.z, ux.w + bU.w};
            float ga[4] = {gx.x + bC.x, gx.y + bC.y, gx.z + bC.z, gx.w + bC.w};
            float oa[4] = {ox.x + bO.x, ox.y + bO.y, ox.z + bO.z, ox.w + bO.w};
            float cv[4] = {c4.x, c4.y, c4.z, c4.w};
            __half hh4[4], hl4[4];
            #pragma unroll
            for (int j = 0; j < 4; ++j) {
                float fv = sigmoidf_(fa[j]);
                float uv = sigmoidf_(ua[j]);
                float gv = tanhf(ga[j]);
                float ov = sigmoidf_(oa[j]);
                float cn = fv * cv[j] + uv * gv;
                cv[j] = cn;
                float hn = ov * tanhf(cn);
                __half hi = __float2half(hn);
                hh4[j] = hi;
                hl4[j] = __float2half(hn - __half2float(hi));
            }
            *(float4*)&g_c[gidx] = make_float4(cv[0], cv[1], cv[2], cv[3]);
            *(uint2*)&hhw[gidx] = *(uint2*)hh4;
            *(uint2*)&hlw[gidx] = *(uint2*)hl4;
        }
        __syncthreads();
    }
}

// ---------------- head ----------------
__global__ void head_kernel(float* __restrict__ out) {
    int w = threadIdx.x >> 5;
    int lane = threadIdx.x & 31;
    int r = blockIdx.x * 8 + w;
    if (r >= BATCH) return;
    const __half* __restrict__ hh = g_hh[TSTEPS & 1] + (size_t)r * HDIM;
    const __half* __restrict__ hl = g_hl[TSTEPS & 1] + (size_t)r * HDIM;
    float s = 0.0f;
    #pragma unroll
    for (int k = lane; k < HDIM; k += 32)
        s += (__half2float(hh[k]) + __half2float(hl[k])) * g_weff[k];
    #pragma unroll
    for (int off = 16; off > 0; off >>= 1) s += __shfl_down_sync(0xffffffffu, s, off);
    if (lane == 0) out[r] = s + g_beff;
}

// ---------------- launch ----------------
extern "C" void kernel_launch(void* const* d_in, const int* in_sizes, int n_in,
                              void* d_out, int out_size) {
    const float* x   = (const float*)d_in[0];
    const float* Wf  = (const float*)d_in[1];
    const float* bf  = (const float*)d_in[2];
    const float* Wu  = (const float*)d_in[3];
    const float* bu  = (const float*)d_in[4];
    const float* Wc  = (const float*)d_in[5];
    const float* bc  = (const float*)d_in[6];
    const float* Wo  = (const float*)d_in[7];
    const float* bo  = (const float*)d_in[8];
    const float* Wd1 = (const float*)d_in[9];
    const float* bd1 = (const float*)d_in[10];
    const float* Wd2 = (const float*)d_in[11];
    const float* bd2 = (const float*)d_in[12];
    float* out = (float*)d_out;

    static bool attr_set = false;
    if (!attr_set) {
        cudaFuncSetAttribute(lstm_step_mma, cudaFuncAttributeMaxDynamicSharedMemorySize, SMEM_TOTAL);
        attr_set = true;
    }

    init_state_kernel<<<(BATCH * HDIM + 255) / 256, 256>>>();
    split_x_kernel<<<(BATCH * TSTEPS * FDIM + 255) / 256, 256>>>(x);
    build_WT_kernel<<<1024, 128>>>(Wf, Wu, Wc, Wo);
    weff_kernel<<<1, HDIM>>>(Wd1, bd1, Wd2, bd2);

    dim3 grid(BATCH / 128, 4);
    for (int t = 0; t < TSTEPS; ++t) {
        lstm_step_mma<<<grid, 256, SMEM_TOTAL>>>(bf, bu, bc, bo, t);
    }

    head_kernel<<<BATCH / 8, 256>>>(out);
}

// round 6
// speedup vs baseline: 2.4852x; 1.4665x over previous
#include <cuda_runtime.h>
#include <cuda_fp16.h>
#include <math.h>
#include <cstdint>

#define BATCH 4096
#define TSTEPS 60
#define FDIM 128
#define HDIM 256
#define FH 384

// ---------------- device scratch (allocation-free rule) ----------------
__device__ __half g_xh[(size_t)BATCH * TSTEPS * FDIM];
__device__ __half g_xl[(size_t)BATCH * TSTEPS * FDIM];
__device__ __half g_hh[2][(size_t)BATCH * HDIM];
__device__ __half g_hl[2][(size_t)BATCH * HDIM];
__device__ float  g_c[(size_t)BATCH * HDIM];
__device__ __half g_Wh[(size_t)1024 * FH];   // [gate*256+col][k]
__device__ __half g_Wl[(size_t)1024 * FH];
__device__ float  g_weff[HDIM];
__device__ float  g_beff;

__device__ __forceinline__ float sigmoidf_(float x) { return 1.0f / (1.0f + __expf(-x)); }

__device__ __forceinline__ uint32_t smem_u32(const void* p) {
    uint32_t a;
    asm("{ .reg .u64 t; cvta.to.shared.u64 t, %1; cvt.u32.u64 %0, t; }" : "=r"(a) : "l"(p));
    return a;
}

#define LD4(R, ADDR) \
    asm volatile("ldmatrix.sync.aligned.m8n8.x4.shared.b16 {%0,%1,%2,%3}, [%4];" \
        : "=r"((R)[0]), "=r"((R)[1]), "=r"((R)[2]), "=r"((R)[3]) : "r"(ADDR))

#define MMA16816(C, A, B0, B1) \
    asm volatile("mma.sync.aligned.m16n8k16.row.col.f32.f16.f16.f32 " \
        "{%0,%1,%2,%3}, {%4,%5,%6,%7}, {%8,%9}, {%0,%1,%2,%3};" \
        : "+f"((C)[0]), "+f"((C)[1]), "+f"((C)[2]), "+f"((C)[3]) \
        : "r"((A)[0]), "r"((A)[1]), "r"((A)[2]), "r"((A)[3]), "r"(B0), "r"(B1))

#define CP16(SADDR, GADDR) \
    asm volatile("cp.async.cg.shared.global [%0], [%1], 16;" :: "r"(SADDR), "l"(GADDR))
#define CP_COMMIT() asm volatile("cp.async.commit_group;")
#define CP_WAIT1() asm volatile("cp.async.wait_group 1;")
#define CP_WAIT0() asm volatile("cp.async.wait_group 0;")

// ---------------- prep kernels ----------------
__global__ void init_state_kernel() {
    size_t i = (size_t)blockIdx.x * blockDim.x + threadIdx.x;
    if (i < (size_t)BATCH * HDIM) {
        g_hh[0][i] = __float2half(0.0f);
        g_hl[0][i] = __float2half(0.0f);
        g_c[i] = 0.0f;
    }
}

__global__ void split_x_kernel(const float* __restrict__ x) {
    size_t i = (size_t)blockIdx.x * blockDim.x + threadIdx.x;
    if (i < (size_t)BATCH * TSTEPS * FDIM) {
        float v = x[i];
        __half hi = __float2half(v);
        g_xh[i] = hi;
        g_xl[i] = __float2half(v - __half2float(hi));
    }
}

__global__ void build_WT_kernel(const float* __restrict__ Wf, const float* __restrict__ Wu,
                                const float* __restrict__ Wc, const float* __restrict__ Wo) {
    int gr = blockIdx.x;                 // 0..1023
    int g = gr >> 8, col = gr & 255;
    const float* W = (g == 0) ? Wf : (g == 1) ? Wu : (g == 2) ? Wc : Wo;
    for (int k = threadIdx.x; k < FH; k += blockDim.x) {
        float w = W[(size_t)k * HDIM + col];
        __half hi = __float2half(w);
        g_Wh[(size_t)gr * FH + k] = hi;
        g_Wl[(size_t)gr * FH + k] = __float2half(w - __half2float(hi));
    }
}

// one warp per output column; coalesced reads
__global__ void weff_kernel(const float* __restrict__ Wd1, const float* __restrict__ bd1,
                            const float* __restrict__ Wd2, const float* __restrict__ bd2) {
    int w = (blockIdx.x * blockDim.x + threadIdx.x) >> 5;   // 0..255
    int lane = threadIdx.x & 31;
    if (w < HDIM) {
        float s = 0.0f;
        #pragma unroll
        for (int k = lane; k < HDIM; k += 32) s += Wd1[(size_t)w * HDIM + k] * Wd2[k];
        #pragma unroll
        for (int off = 16; off > 0; off >>= 1) s += __shfl_down_sync(0xffffffffu, s, off);
        if (lane == 0) g_weff[w] = s;
    }
    if (blockIdx.x == 0 && threadIdx.x < 32) {
        float b = 0.0f;
        #pragma unroll
        for (int k = lane; k < HDIM; k += 32) b += bd1[k] * Wd2[k];
        #pragma unroll
        for (int off = 16; off > 0; off >>= 1) b += __shfl_down_sync(0xffffffffu, b, off);
        if (lane == 0) g_beff = b + bd2[0];
    }
}

// ---------------- step kernel (mma.sync fp16x3, 512 threads) ----------------
// smem: per buffer  A rows 128 x 80B (hi,lo)  B rows 256 x 80B (hi,lo)
#define A_HI 0
#define A_LO 10240
#define B_HI 20480
#define B_LO 40960
#define BUF_SZ 61440
#define SMEM_TOTAL (2 * BUF_SZ)   // 120 KB

__global__ __launch_bounds__(512, 1)
void lstm_step_mma(const float* __restrict__ bfv, const float* __restrict__ buv,
                   const float* __restrict__ bcv, const float* __restrict__ bov, int t) {
    extern __shared__ __align__(128) char smem[];
    const uint32_t sbase = smem_u32(smem);
    const int tid = threadIdx.x;
    const int warp = tid >> 5;
    const int lane = tid & 31;
    const int wm = warp >> 2;      // 0..3 : 32-row band
    const int wn = warp & 3;       // 0..3 : 16-col band within the 64-col slice
    const int m0 = blockIdx.x * 128;
    const int ny = blockIdx.y;     // 64-col hidden slice

    const __half* __restrict__ hhr = g_hh[t & 1];
    const __half* __restrict__ hlr = g_hl[t & 1];
    __half* __restrict__ hhw = g_hh[(t + 1) & 1];
    __half* __restrict__ hlw = g_hl[(t + 1) & 1];

    // acc[gate][i(m16)][s2(n8)][4]
    float acc[4][2][2][4];
    #pragma unroll
    for (int g = 0; g < 4; ++g)
        #pragma unroll
        for (int i = 0; i < 2; ++i)
            #pragma unroll
            for (int s = 0; s < 2; ++s)
                #pragma unroll
                for (int q = 0; q < 4; ++q) acc[g][i][s][q] = 0.0f;

    // ---- cp.async chunk loader: 6 x 16B per thread ----
    auto issue_chunk = [&](int c) {
        char* bb = smem + (c & 1) * BUF_SZ;
        // A hi/lo: 128 rows x 64B, op t: row=t>>2, seg=t&3
        {
            int row = tid >> 2, seg = tid & 3;
            const __half *ph, *pl;
            size_t s;
            if (c < 4) {
                s = ((size_t)(m0 + row) * TSTEPS + t) * FDIM + c * 32 + seg * 8;
                ph = g_xh; pl = g_xl;
            } else {
                s = (size_t)(m0 + row) * HDIM + (c - 4) * 32 + seg * 8;
                ph = hhr; pl = hlr;
            }
            uint32_t d = smem_u32(bb) + (uint32_t)(row * 80 + seg * 16);
            CP16(d + A_HI, &ph[s]);
            CP16(d + A_LO, &pl[s]);
        }
        // B hi/lo: 256 rows x 64B -> 1024 ops per half, 2 per thread per half
        #pragma unroll
        for (int e = 0; e < 2; ++e) {
            int idx = tid + e * 512;         // 0..1023
            int row = idx >> 2, seg = idx & 3;
            int gr = ((row >> 6) << 8) + ny * 64 + (row & 63);
            size_t s = (size_t)gr * FH + c * 32 + seg * 8;
            uint32_t d = smem_u32(bb) + (uint32_t)(row * 80 + seg * 16);
            CP16(d + B_HI, &g_Wh[s]);
            CP16(d + B_LO, &g_Wl[s]);
        }
        CP_COMMIT();
    };

    const int grp = lane >> 3, lr = lane & 7;

    issue_chunk(0);
    issue_chunk(1);

    for (int c = 0; c < 12; ++c) {
        if (c < 11) { CP_WAIT1(); } else { CP_WAIT0(); }
        __syncthreads();

        const uint32_t bufb = sbase + (uint32_t)((c & 1) * BUF_SZ);
        #pragma unroll
        for (int kh = 0; kh < 2; ++kh) {
            uint32_t ah[2][4], al[2][4];
            const int acol = kh * 32 + (grp >> 1) * 16;
            #pragma unroll
            for (int i = 0; i < 2; ++i) {
                int arow = wm * 32 + i * 16 + (grp & 1) * 8 + lr;
                uint32_t ad = bufb + A_HI + (uint32_t)(arow * 80 + acol);
                LD4(ah[i], ad);
                LD4(al[i], ad + (A_LO - A_HI));
            }
            const int bcol = kh * 32 + (grp & 1) * 16;
            #pragma unroll
            for (int g = 0; g < 4; ++g) {
                uint32_t bh[4], bl[4];
                int brow = g * 64 + wn * 16 + ((grp >> 1) << 3) + lr;
                uint32_t bd = bufb + B_HI + (uint32_t)(brow * 80 + bcol);
                LD4(bh, bd);
                LD4(bl, bd + (B_LO - B_HI));
                #pragma unroll
                for (int i = 0; i < 2; ++i)
                    #pragma unroll
                    for (int s2 = 0; s2 < 2; ++s2) {
                        MMA16816(acc[g][i][s2], ah[i], bh[s2 * 2], bh[s2 * 2 + 1]);
                        MMA16816(acc[g][i][s2], ah[i], bl[s2 * 2], bl[s2 * 2 + 1]);
                        MMA16816(acc[g][i][s2], al[i], bh[s2 * 2], bh[s2 * 2 + 1]);
                    }
            }
        }
        __syncthreads();
        if (c + 2 < 12) issue_chunk(c + 2);
    }

    // ---- epilogue: fully register-local (warp owns all 4 gates of its patch) ----
    #pragma unroll
    for (int i = 0; i < 2; ++i)
        #pragma unroll
        for (int s2 = 0; s2 < 2; ++s2) {
            const int col = ny * 64 + wn * 16 + s2 * 8 + (lane & 3) * 2;
            float2 bF = *(const float2*)&bfv[col];
            float2 bU = *(const float2*)&buv[col];
            float2 bC = *(const float2*)&bcv[col];
            float2 bO = *(const float2*)&bov[col];
            #pragma unroll
            for (int rh = 0; rh < 2; ++rh) {
                int row = m0 + wm * 32 + i * 16 + (lane >> 2) + rh * 8;
                size_t gi = (size_t)row * HDIM + col;
                float2 c2 = *(float2*)&g_c[gi];
                float fa0 = acc[0][i][s2][rh * 2 + 0] + bF.x;
                float fa1 = acc[0][i][s2][rh * 2 + 1] + bF.y;
                float ua0 = acc[1][i][s2][rh * 2 + 0] + bU.x;
                float ua1 = acc[1][i][s2][rh * 2 + 1] + bU.y;
                float ga0 = acc[2][i][s2][rh * 2 + 0] + bC.x;
                float ga1 = acc[2][i][s2][rh * 2 + 1] + bC.y;
                float oa0 = acc[3][i][s2][rh * 2 + 0] + bO.x;
                float oa1 = acc[3][i][s2][rh * 2 + 1] + bO.y;
                float cn0 = sigmoidf_(fa0) * c2.x + sigmoidf_(ua0) * tanhf(ga0);
                float cn1 = sigmoidf_(fa1) * c2.y + sigmoidf_(ua1) * tanhf(ga1);
                float hn0 = sigmoidf_(oa0) * tanhf(cn0);
                float hn1 = sigmoidf_(oa1) * tanhf(cn1);
                *(float2*)&g_c[gi] = make_float2(cn0, cn1);
                __half h0 = __float2half(hn0), h1 = __float2half(hn1);
                __half l0 = __float2half(hn0 - __half2float(h0));
                __half l1 = __float2half(hn1 - __half2float(h1));
                *(__half2*)&hhw[gi] = __halves2half2(h0, h1);
                *(__half2*)&hlw[gi] = __halves2half2(l0, l1);
            }
        }
}

// ---------------- head ----------------
__global__ void head_kernel(float* __restrict__ out) {
    int w = threadIdx.x >> 5;
    int lane = threadIdx.x & 31;
    int r = blockIdx.x * 8 + w;
    if (r >= BATCH) return;
    const __half* __restrict__ hh = g_hh[TSTEPS & 1] + (size_t)r * HDIM;
    const __half* __restrict__ hl = g_hl[TSTEPS & 1] + (size_t)r * HDIM;
    float s = 0.0f;
    #pragma unroll
    for (int k = lane; k < HDIM; k += 32)
        s += (__half2float(hh[k]) + __half2float(hl[k])) * g_weff[k];
    #pragma unroll
    for (int off = 16; off > 0; off >>= 1) s += __shfl_down_sync(0xffffffffu, s, off);
    if (lane == 0) out[r] = s + g_beff;
}

// ---------------- launch ----------------
extern "C" void kernel_launch(void* const* d_in, const int* in_sizes, int n_in,
                              void* d_out, int out_size) {
    const float* x   = (const float*)d_in[0];
    const float* Wf  = (const float*)d_in[1];
    const float* bf  = (const float*)d_in[2];
    const float* Wu  = (const float*)d_in[3];
    const float* bu  = (const float*)d_in[4];
    const float* Wc  = (const float*)d_in[5];
    const float* bc  = (const float*)d_in[6];
    const float* Wo  = (const float*)d_in[7];
    const float* bo  = (const float*)d_in[8];
    const float* Wd1 = (const float*)d_in[9];
    const float* bd1 = (const float*)d_in[10];
    const float* Wd2 = (const float*)d_in[11];
    const float* bd2 = (const float*)d_in[12];
    float* out = (float*)d_out;

    static bool attr_set = false;
    if (!attr_set) {
        cudaFuncSetAttribute(lstm_step_mma, cudaFuncAttributeMaxDynamicSharedMemorySize, SMEM_TOTAL);
        attr_set = true;
    }

    init_state_kernel<<<(BATCH * HDIM + 255) / 256, 256>>>();
    split_x_kernel<<<(BATCH * TSTEPS * FDIM + 255) / 256, 256>>>(x);
    build_WT_kernel<<<1024, 128>>>(Wf, Wu, Wc, Wo);
    weff_kernel<<<8, 1024>>>(Wd1, bd1, Wd2, bd2);

    dim3 grid(BATCH / 128, 4);
    for (int t = 0; t < TSTEPS; ++t) {
        lstm_step_mma<<<grid, 512, SMEM_TOTAL>>>(bf, bu, bc, bo, t);
    }

    head_kernel<<<BATCH / 8, 256>>>(out);
}

// round 7
// speedup vs baseline: 3.2049x; 1.2896x over previous
#include <cuda_runtime.h>
#include <cuda_fp16.h>
#include <math.h>
#include <cstdint>

#define BATCH 4096
#define TSTEPS 60
#define FDIM 128
#define HDIM 256
#define FH 384

// ---------------- device scratch (allocation-free rule) ----------------
__device__ __half g_xh[(size_t)BATCH * TSTEPS * FDIM];
__device__ __half g_hh[2][(size_t)BATCH * HDIM];
__device__ float  g_c[(size_t)BATCH * HDIM];
__device__ __half g_Wh[(size_t)1024 * FH];   // [gate*256+col][k]
__device__ __half g_Wl[(size_t)1024 * FH];
__device__ float  g_weff[HDIM];
__device__ float  g_beff;

__device__ __forceinline__ float sigmoidf_(float x) { return 1.0f / (1.0f + __expf(-x)); }

__device__ __forceinline__ uint32_t smem_u32(const void* p) {
    uint32_t a;
    asm("{ .reg .u64 t; cvta.to.shared.u64 t, %1; cvt.u32.u64 %0, t; }" : "=r"(a) : "l"(p));
    return a;
}

#define LD4(R, ADDR) \
    asm volatile("ldmatrix.sync.aligned.m8n8.x4.shared.b16 {%0,%1,%2,%3}, [%4];" \
        : "=r"((R)[0]), "=r"((R)[1]), "=r"((R)[2]), "=r"((R)[3]) : "r"(ADDR))

#define MMA16816(C, A, B0, B1) \
    asm volatile("mma.sync.aligned.m16n8k16.row.col.f32.f16.f16.f32 " \
        "{%0,%1,%2,%3}, {%4,%5,%6,%7}, {%8,%9}, {%0,%1,%2,%3};" \
        : "+f"((C)[0]), "+f"((C)[1]), "+f"((C)[2]), "+f"((C)[3]) \
        : "r"((A)[0]), "r"((A)[1]), "r"((A)[2]), "r"((A)[3]), "r"(B0), "r"(B1))

#define CP16(SADDR, GADDR) \
    asm volatile("cp.async.cg.shared.global [%0], [%1], 16;" :: "r"(SADDR), "l"(GADDR))
#define CP_COMMIT() asm volatile("cp.async.commit_group;")
#define CP_WAITG(N) asm volatile("cp.async.wait_group %0;" :: "n"(N))

// ---------------- prep kernels ----------------
__global__ void init_state_kernel() {
    size_t i = (size_t)blockIdx.x * blockDim.x + threadIdx.x;
    if (i < (size_t)BATCH * HDIM) {
        g_hh[0][i] = __float2half(0.0f);
        g_c[i] = 0.0f;
    }
}

__global__ void split_x_kernel(const float* __restrict__ x) {
    size_t i = (size_t)blockIdx.x * blockDim.x + threadIdx.x;
    if (i < (size_t)BATCH * TSTEPS * FDIM) {
        g_xh[i] = __float2half(x[i]);
    }
}

__global__ void build_WT_kernel(const float* __restrict__ Wf, const float* __restrict__ Wu,
                                const float* __restrict__ Wc, const float* __restrict__ Wo) {
    int gr = blockIdx.x;                 // 0..1023
    int g = gr >> 8, col = gr & 255;
    const float* W = (g == 0) ? Wf : (g == 1) ? Wu : (g == 2) ? Wc : Wo;
    for (int k = threadIdx.x; k < FH; k += blockDim.x) {
        float w = W[(size_t)k * HDIM + col];
        __half hi = __float2half(w);
        g_Wh[(size_t)gr * FH + k] = hi;
        g_Wl[(size_t)gr * FH + k] = __float2half(w - __half2float(hi));
    }
}

// one warp per output column; coalesced reads
__global__ void weff_kernel(const float* __restrict__ Wd1, const float* __restrict__ bd1,
                            const float* __restrict__ Wd2, const float* __restrict__ bd2) {
    int w = (blockIdx.x * blockDim.x + threadIdx.x) >> 5;   // 0..255
    int lane = threadIdx.x & 31;
    if (w < HDIM) {
        float s = 0.0f;
        #pragma unroll
        for (int k = lane; k < HDIM; k += 32) s += Wd1[(size_t)w * HDIM + k] * Wd2[k];
        #pragma unroll
        for (int off = 16; off > 0; off >>= 1) s += __shfl_down_sync(0xffffffffu, s, off);
        if (lane == 0) g_weff[w] = s;
    }
    if (blockIdx.x == 0 && threadIdx.x < 32) {
        float b = 0.0f;
        #pragma unroll
        for (int k = lane; k < HDIM; k += 32) b += bd1[k] * Wd2[k];
        #pragma unroll
        for (int off = 16; off > 0; off >>= 1) b += __shfl_down_sync(0xffffffffu, b, off);
        if (lane == 0) g_beff = b + bd2[0];
    }
}

// ---------------- step kernel (mma.sync fp16x2, 512 threads, 3-stage pipe) ----------------
// per stage: A 128 rows x 80B, B_HI 256 x 80B, B_LO 256 x 80B
#define A_OFF 0
#define B_HI  10240
#define B_LO  30720
#define STAGE_SZ 51200
#define NSTAGE 3
#define SMEM_TOTAL (NSTAGE * STAGE_SZ)   // 150 KB

__global__ __launch_bounds__(512, 1)
void lstm_step_mma(const float* __restrict__ bfv, const float* __restrict__ buv,
                   const float* __restrict__ bcv, const float* __restrict__ bov, int t) {
    extern __shared__ __align__(128) char smem[];
    const uint32_t sbase = smem_u32(smem);
    const int tid = threadIdx.x;
    const int warp = tid >> 5;
    const int lane = tid & 31;
    const int wm = warp >> 2;      // 0..3 : 32-row band
    const int wn = warp & 3;       // 0..3 : 16-col band within the 64-col slice
    const int m0 = blockIdx.x * 128;
    const int ny = blockIdx.y;     // 64-col hidden slice

    const __half* __restrict__ hhr = g_hh[t & 1];
    __half* __restrict__ hhw = g_hh[(t + 1) & 1];

    // acc[gate][i(m16)][s2(n8)][4]
    float acc[4][2][2][4];
    #pragma unroll
    for (int g = 0; g < 4; ++g)
        #pragma unroll
        for (int i = 0; i < 2; ++i)
            #pragma unroll
            for (int s = 0; s < 2; ++s)
                #pragma unroll
                for (int q = 0; q < 4; ++q) acc[g][i][s][q] = 0.0f;

    // ---- cp.async chunk loader: 5 x 16B per thread ----
    auto issue_chunk = [&](int c) {
        uint32_t bb = sbase + (uint32_t)((c % NSTAGE) * STAGE_SZ);
        // A: 128 rows x 64B -> 512 x 16B ops, 1 per thread
        {
            int row = tid >> 2, seg = tid & 3;
            const __half* ph;
            size_t s;
            if (c < 4) {
                s = ((size_t)(m0 + row) * TSTEPS + t) * FDIM + c * 32 + seg * 8;
                ph = g_xh;
            } else {
                s = (size_t)(m0 + row) * HDIM + (c - 4) * 32 + seg * 8;
                ph = hhr;
            }
            CP16(bb + A_OFF + (uint32_t)(row * 80 + seg * 16), &ph[s]);
        }
        // B hi/lo: 256 rows x 64B -> 1024 x 16B per half, 2 per thread per half
        #pragma unroll
        for (int e = 0; e < 2; ++e) {
            int idx = tid + e * 512;         // 0..1023
            int row = idx >> 2, seg = idx & 3;
            int gr = ((row >> 6) << 8) + ny * 64 + (row & 63);
            size_t s = (size_t)gr * FH + c * 32 + seg * 8;
            uint32_t d = bb + (uint32_t)(row * 80 + seg * 16);
            CP16(d + B_HI, &g_Wh[s]);
            CP16(d + B_LO, &g_Wl[s]);
        }
        CP_COMMIT();
    };

    const int grp = lane >> 3, lr = lane & 7;

    issue_chunk(0);
    issue_chunk(1);

    for (int c = 0; c < 12; ++c) {
        if (c < 11) { CP_WAITG(1); } else { CP_WAITG(0); }
        __syncthreads();
        if (c + 2 < 12) issue_chunk(c + 2);   // buf (c+2)%3: distinct from c, c+1; prev compute ordered by the barrier

        const uint32_t bufb = sbase + (uint32_t)((c % NSTAGE) * STAGE_SZ);
        #pragma unroll
        for (int kh = 0; kh < 2; ++kh) {
            uint32_t ah[2][4];
            const int acol = kh * 32 + (grp >> 1) * 16;
            #pragma unroll
            for (int i = 0; i < 2; ++i) {
                int arow = wm * 32 + i * 16 + (grp & 1) * 8 + lr;
                LD4(ah[i], bufb + A_OFF + (uint32_t)(arow * 80 + acol));
            }
            const int bcol = kh * 32 + (grp & 1) * 16;
            #pragma unroll
            for (int g = 0; g < 4; ++g) {
                uint32_t bh[4], bl[4];
                int brow = g * 64 + wn * 16 + ((grp >> 1) << 3) + lr;
                uint32_t bd = bufb + B_HI + (uint32_t)(brow * 80 + bcol);
                LD4(bh, bd);
                LD4(bl, bd + (B_LO - B_HI));
                #pragma unroll
                for (int i = 0; i < 2; ++i)
                    #pragma unroll
                    for (int s2 = 0; s2 < 2; ++s2) {
                        MMA16816(acc[g][i][s2], ah[i], bh[s2 * 2], bh[s2 * 2 + 1]);
                        MMA16816(acc[g][i][s2], ah[i], bl[s2 * 2], bl[s2 * 2 + 1]);
                    }
            }
        }
    }

    // ---- epilogue: fully register-local (warp owns all 4 gates of its patch) ----
    #pragma unroll
    for (int i = 0; i < 2; ++i)
        #pragma unroll
        for (int s2 = 0; s2 < 2; ++s2) {
            const int col = ny * 64 + wn * 16 + s2 * 8 + (lane & 3) * 2;
            float2 bF = *(const float2*)&bfv[col];
            float2 bU = *(const float2*)&buv[col];
            float2 bC = *(const float2*)&bcv[col];
            float2 bO = *(const float2*)&bov[col];
            #pragma unroll
            for (int rh = 0; rh < 2; ++rh) {
                int row = m0 + wm * 32 + i * 16 + (lane >> 2) + rh * 8;
                size_t gi = (size_t)row * HDIM + col;
                float2 c2 = *(float2*)&g_c[gi];
                float fa0 = acc[0][i][s2][rh * 2 + 0] + bF.x;
                float fa1 = acc[0][i][s2][rh * 2 + 1] + bF.y;
                float ua0 = acc[1][i][s2][rh * 2 + 0] + bU.x;
                float ua1 = acc[1][i][s2][rh * 2 + 1] + bU.y;
                float ga0 = acc[2][i][s2][rh * 2 + 0] + bC.x;
                float ga1 = acc[2][i][s2][rh * 2 + 1] + bC.y;
                float oa0 = acc[3][i][s2][rh * 2 + 0] + bO.x;
                float oa1 = acc[3][i][s2][rh * 2 + 1] + bO.y;
                float cn0 = sigmoidf_(fa0) * c2.x + sigmoidf_(ua0) * tanhf(ga0);
                float cn1 = sigmoidf_(fa1) * c2.y + sigmoidf_(ua1) * tanhf(ga1);
                float hn0 = sigmoidf_(oa0) * tanhf(cn0);
                float hn1 = sigmoidf_(oa1) * tanhf(cn1);
                *(float2*)&g_c[gi] = make_float2(cn0, cn1);
                *(__half2*)&hhw[gi] = __halves2half2(__float2half(hn0), __float2half(hn1));
            }
        }
}

// ---------------- head ----------------
__global__ void head_kernel(float* __restrict__ out) {
    int w = threadIdx.x >> 5;
    int lane = threadIdx.x & 31;
    int r = blockIdx.x * 8 + w;
    if (r >= BATCH) return;
    const __half* __restrict__ hh = g_hh[TSTEPS & 1] + (size_t)r * HDIM;
    float s = 0.0f;
    #pragma unroll
    for (int k = lane; k < HDIM; k += 32)
        s += __half2float(hh[k]) * g_weff[k];
    #pragma unroll
    for (int off = 16; off > 0; off >>= 1) s += __shfl_down_sync(0xffffffffu, s, off);
    if (lane == 0) out[r] = s + g_beff;
}

// ---------------- launch ----------------
extern "C" void kernel_launch(void* const* d_in, const int* in_sizes, int n_in,
                              void* d_out, int out_size) {
    const float* x   = (const float*)d_in[0];
    const float* Wf  = (const float*)d_in[1];
    const float* bf  = (const float*)d_in[2];
    const float* Wu  = (const float*)d_in[3];
    const float* bu  = (const float*)d_in[4];
    const float* Wc  = (const float*)d_in[5];
    const float* bc  = (const float*)d_in[6];
    const float* Wo  = (const float*)d_in[7];
    const float* bo  = (const float*)d_in[8];
    const float* Wd1 = (const float*)d_in[9];
    const float* bd1 = (const float*)d_in[10];
    const float* Wd2 = (const float*)d_in[11];
    const float* bd2 = (const float*)d_in[12];
    float* out = (float*)d_out;

    static bool attr_set = false;
    if (!attr_set) {
        cudaFuncSetAttribute(lstm_step_mma, cudaFuncAttributeMaxDynamicSharedMemorySize, SMEM_TOTAL);
        attr_set = true;
    }

    init_state_kernel<<<(BATCH * HDIM + 255) / 256, 256>>>();
    split_x_kernel<<<(BATCH * TSTEPS * FDIM + 255) / 256, 256>>>(x);
    build_WT_kernel<<<1024, 128>>>(Wf, Wu, Wc, Wo);
    weff_kernel<<<8, 1024>>>(Wd1, bd1, Wd2, bd2);

    dim3 grid(BATCH / 128, 4);
    for (int t = 0; t < TSTEPS; ++t) {
        lstm_step_mma<<<grid, 512, SMEM_TOTAL>>>(bf, bu, bc, bo, t);
    }

    head_kernel<<<BATCH / 8, 256>>>(out);
}